// round 13
// baseline (speedup 1.0000x reference)
#include <cuda_runtime.h>
#include <math.h>

#define DIMC   2048
#define NH     16
#define HD     128
#define T_SEQ  512
#define BATCH  16
#define BH     (BATCH * NH)      // 256
#define NTOK   (BATCH * T_SEQ)   // 8192
#define N_QKV  (3 * DIMC)        // 6144
#define GKD    2048

// Scratch (device globals; no allocations allowed)
__device__ float g_Q[BH * T_SEQ * HD];
__device__ float g_K[BH * T_SEQ * HD];
__device__ float g_V[BH * T_SEQ * HD];
__device__ float g_Y[NTOK * DIMC];        // attention out, tf32-rounded
__device__ float g_xr[NTOK * DIMC];       // x, tf32-rounded
__device__ float g_WqkvT[N_QKV * DIMC];   // [6144][2048], tf32-rounded
__device__ float g_WoutT[DIMC * DIMC];    // [2048][2048], tf32-rounded

// ---------------------------------------------------------------------------
__device__ __forceinline__ float to_tf32(float x) {
    float y;
    asm("cvt.rna.tf32.f32 %0, %1;" : "=f"(y) : "f"(x));
    return y;
}
__device__ __forceinline__ unsigned smem_u32(const void* p) {
    unsigned a;
    asm("{ .reg .u64 t; cvta.to.shared.u64 t, %1; cvt.u32.u64 %0, t; }"
        : "=r"(a) : "l"(p));
    return a;
}
__device__ __forceinline__ void mma8(float* c,
                                     unsigned a0, unsigned a1, unsigned a2, unsigned a3,
                                     unsigned b0, unsigned b1) {
    asm volatile(
        "mma.sync.aligned.m16n8k8.row.col.f32.tf32.tf32.f32 "
        "{%0,%1,%2,%3}, {%4,%5,%6,%7}, {%8,%9}, {%0,%1,%2,%3};"
        : "+f"(c[0]), "+f"(c[1]), "+f"(c[2]), "+f"(c[3])
        : "r"(a0), "r"(a1), "r"(a2), "r"(a3), "r"(b0), "r"(b1));
}

// ---------------------------------------------------------------------------
// Fused pre-pass: round x + both weight transposes (one launch).
// ---------------------------------------------------------------------------
#define NXB (NTOK * DIMC / 4 / 256)       // 16384
#define NQB ((N_QKV / 32) * (DIMC / 32))  // 12288
#define NOB ((DIMC / 32) * (DIMC / 32))   // 4096

__global__ __launch_bounds__(256)
void prep_kernel(const float* __restrict__ x,
                 const float* __restrict__ Wqkv,
                 const float* __restrict__ Wout)
{
    __shared__ float t[32][33];
    int b = blockIdx.x;
    int tid = threadIdx.x;

    if (b < NXB) {
        long i = (long)b * 256 + tid;     // float4 index
        float4 v = *(const float4*)(x + i * 4);
        v.x = to_tf32(v.x); v.y = to_tf32(v.y);
        v.z = to_tf32(v.z); v.w = to_tf32(v.w);
        *(float4*)(g_xr + i * 4) = v;
        return;
    }

    const float* W;
    float* Wt;
    int N, bb;
    if (b < NXB + NQB) {
        bb = b - NXB; W = Wqkv; Wt = g_WqkvT; N = N_QKV;
    } else {
        bb = b - NXB - NQB; W = Wout; Wt = g_WoutT; N = DIMC;
    }
    int nblk = N / 32;
    int n0 = (bb % nblk) * 32, k0 = (bb / nblk) * 32;
    int tx = tid & 31, ty = tid >> 5;   // 32 x 8
#pragma unroll
    for (int i = 0; i < 32; i += 8)
        t[ty + i][tx] = to_tf32(W[(long)(k0 + ty + i) * N + n0 + tx]);
    __syncthreads();
#pragma unroll
    for (int i = 0; i < 32; i += 8)
        Wt[(long)(n0 + ty + i) * GKD + k0 + tx] = t[tx][ty + i];
}

// ---------------------------------------------------------------------------
// TF32 mma.sync GEMM: BM=128 BN=128 BK=32, 512 threads, 16 warps of 32x32
// warp tiles (4x4), 3-stage cp.async, one __syncthreads per iteration.
// 8 warps/SMSP for latency hiding; acc=32 regs -> fits 64-reg 2-CTA cap.
// MODE 0: A=g_xr, B=g_WqkvT -> scatter g_Q/g_K/g_V ; MODE 1: A=g_Y -> out
// ---------------------------------------------------------------------------
#define BKP 36
#define TILE_F (128 * BKP)            // 4608 floats
#define STAGE_F (2 * TILE_F)          // 9216 floats
#define NSTAGE 3
#define GEMM_SMEM (NSTAGE * STAGE_F * 4)   // 110592 bytes

template <int MODE>
__global__ __launch_bounds__(512, 2)
void gemm_mma_kernel(float* __restrict__ Cmat, int N)
{
    extern __shared__ float sm[];

    const float* A  = (MODE == 0) ? g_xr : g_Y;
    const float* Bt = (MODE == 0) ? g_WqkvT : g_WoutT;

    int tid = threadIdx.x;
    int wid = tid >> 5;
    int lane = tid & 31;
    int g = lane >> 2;
    int tig = lane & 3;

    int bm = blockIdx.y * 128;
    int bn = blockIdx.x * 128;
    int wm = (wid & 3) * 32;      // 4 warp rows
    int wn = (wid >> 2) * 32;     // 4 warp cols

    const float* Arow = A + (long)bm * GKD;
    const float* Brow = Bt + (long)bn * GKD;

    float acc[2][4][4];
#pragma unroll
    for (int mt = 0; mt < 2; mt++)
#pragma unroll
        for (int nt = 0; nt < 4; nt++)
#pragma unroll
            for (int v = 0; v < 4; v++) acc[mt][nt][v] = 0.f;

    auto load_stage = [&](int it, int st) {
        float* dstA = sm + st * STAGE_F;
        float* dstB = dstA + TILE_F;
        int k0 = it * 32;
#pragma unroll
        for (int i = 0; i < 2; i++) {
            int id = tid + 512 * i;          // 0..1023
            int r = id >> 3, ch = id & 7;
            unsigned da = smem_u32(dstA + r * BKP + ch * 4);
            const float* sa = Arow + (long)r * GKD + k0 + ch * 4;
            asm volatile("cp.async.cg.shared.global [%0], [%1], 16;"
                         :: "r"(da), "l"(sa));
            unsigned db = smem_u32(dstB + r * BKP + ch * 4);
            const float* sb = Brow + (long)r * GKD + k0 + ch * 4;
            asm volatile("cp.async.cg.shared.global [%0], [%1], 16;"
                         :: "r"(db), "l"(sb));
        }
        asm volatile("cp.async.commit_group;" ::: "memory");
    };

    auto compute = [&](const float* s) {
        const float* As = s;
        const float* Bs = s + TILE_F;
#pragma unroll
        for (int ks = 0; ks < 32; ks += 8) {
            unsigned a[2][4];
#pragma unroll
            for (int mt = 0; mt < 2; mt++) {
                int r = wm + 16 * mt + g;
                a[mt][0] = __float_as_uint(As[r * BKP + ks + tig]);
                a[mt][1] = __float_as_uint(As[(r + 8) * BKP + ks + tig]);
                a[mt][2] = __float_as_uint(As[r * BKP + ks + tig + 4]);
                a[mt][3] = __float_as_uint(As[(r + 8) * BKP + ks + tig + 4]);
            }
#pragma unroll
            for (int nt = 0; nt < 4; nt++) {
                int rn = wn + 8 * nt + g;
                unsigned b0 = __float_as_uint(Bs[rn * BKP + ks + tig]);
                unsigned b1 = __float_as_uint(Bs[rn * BKP + ks + tig + 4]);
#pragma unroll
                for (int mt = 0; mt < 2; mt++)
                    mma8(acc[mt][nt], a[mt][0], a[mt][1], a[mt][2], a[mt][3], b0, b1);
            }
        }
    };

    const int NIT = GKD / 32;     // 64
    load_stage(0, 0);
    load_stage(1, 1);

    for (int it = 0; it < NIT; it++) {
        if (it < NIT - 1)
            asm volatile("cp.async.wait_group 1;" ::: "memory");
        else
            asm volatile("cp.async.wait_group 0;" ::: "memory");
        __syncthreads();
        if (it + 2 < NIT) load_stage(it + 2, (it + 2) % NSTAGE);
        compute(sm + (it % NSTAGE) * STAGE_F);
    }

    // epilogue
#pragma unroll
    for (int mt = 0; mt < 2; mt++) {
#pragma unroll
        for (int nt = 0; nt < 4; nt++) {
            int col = bn + wn + 8 * nt + 2 * tig;
#pragma unroll
            for (int half = 0; half < 2; half++) {
                int m = bm + wm + 16 * mt + g + 8 * half;
                float2 v = make_float2(acc[mt][nt][2 * half],
                                       acc[mt][nt][2 * half + 1]);
                if (MODE == 0) {
                    int which = col >> 11;
                    int rm = col & 2047;
                    int h = rm >> 7, d = rm & 127;
                    float* dst = (which == 0) ? g_Q : (which == 1) ? g_K : g_V;
                    *(float2*)(dst + (((long)((m >> 9) * NH + h)) * T_SEQ
                                      + (m & 511)) * HD + d) = v;
                } else {
                    *(float2*)(Cmat + (long)m * N + col) = v;
                }
            }
        }
    }
}

// ---------------------------------------------------------------------------
// Flash v3 (unchanged from R12): Q in registers, 64-query CTAs of 128
// threads, single-buffered K/V smem (69.6 KB -> 2 CTAs/SM), causal tf32 mma.
// ---------------------------------------------------------------------------
#define FL_LD 136
#define FLASH_SMEM (2 * 64 * FL_LD * 4)   // 69632 B

__global__ __launch_bounds__(128)
void flash_mma_kernel()
{
    extern __shared__ float fsm[];
    float* Ks = fsm;                     // [64][FL_LD]
    float* Vs = fsm + 64 * FL_LD;        // [64][FL_LD]

    int bh = blockIdx.y;
    int q0 = blockIdx.x * 64;
    int tid = threadIdx.x;
    int wid = tid >> 5;
    int lane = tid & 31;
    int g = lane >> 2;
    int tig = lane & 3;
    int wm = wid * 16;

    const float* Qg = g_Q + (long)bh * T_SEQ * HD;
    const float* Kg = g_K + (long)bh * T_SEQ * HD;
    const float* Vg = g_V + (long)bh * T_SEQ * HD;

    const float scale = 0.08838834764831845f;
    const unsigned FULL = 0xffffffffu;

    int r0 = q0 + wm + g;
    int r1 = r0 + 8;

    // ---- load Q fragments, rope in-register, scale+round ----
    float qv[16][4];
#pragma unroll
    for (int ks = 0; ks < 16; ks++) {
        qv[ks][0] = Qg[(long)r0 * HD + 8 * ks + tig];
        qv[ks][1] = Qg[(long)r1 * HD + 8 * ks + tig];
        qv[ks][2] = Qg[(long)r0 * HD + 8 * ks + tig + 4];
        qv[ks][3] = Qg[(long)r1 * HD + 8 * ks + tig + 4];
    }
#pragma unroll
    for (int j = 0; j < 4; j++) {
        int i = tig + ((j & 2) ? 4 : 0);
        int rr = (j & 1) ? r1 : r0;
        float inv = powf(10000.f, -(float)i / 8.f);
        float sn, cs;
        sincosf((float)rr * inv, &sn, &cs);
        float x1 = qv[0][j], x2 = qv[1][j];
        qv[0][j] = x1 * cs - x2 * sn;
        qv[1][j] = x2 * cs + x1 * sn;
    }
    unsigned qf[16][4];
#pragma unroll
    for (int ks = 0; ks < 16; ks++)
#pragma unroll
        for (int j = 0; j < 4; j++)
            qf[ks][j] = __float_as_uint(to_tf32(qv[ks][j] * scale));

    float acc_o[16][4];
#pragma unroll
    for (int nto = 0; nto < 16; nto++)
#pragma unroll
        for (int v = 0; v < 4; v++) acc_o[nto][v] = 0.f;
    float mrow0 = -1e30f, mrow1 = -1e30f;
    float lrow0 = 0.f, lrow1 = 0.f;

    int nkt = q0 / 64 + 1;

    for (int kt = 0; kt < nkt; kt++) {
        int k0 = kt * 64;
        __syncthreads();
        {
            const float* ks = Kg + (long)k0 * HD;
            const float* vs = Vg + (long)k0 * HD;
#pragma unroll
            for (int i = tid; i < 2048; i += 128) {
                int r = i >> 5, ch = i & 31;
                unsigned dk = smem_u32(Ks + r * FL_LD + ch * 4);
                asm volatile("cp.async.cg.shared.global [%0], [%1], 16;"
                             :: "r"(dk), "l"(ks + (long)r * HD + ch * 4));
                unsigned dv = smem_u32(Vs + r * FL_LD + ch * 4);
                asm volatile("cp.async.cg.shared.global [%0], [%1], 16;"
                             :: "r"(dv), "l"(vs + (long)r * HD + ch * 4));
            }
            asm volatile("cp.async.commit_group;" ::: "memory");
            asm volatile("cp.async.wait_group 0;" ::: "memory");
        }
        __syncthreads();
        for (int i = tid; i < 512; i += 128) {
            int r = i >> 3, c = i & 7;
            float x1 = Ks[r * FL_LD + c], x2 = Ks[r * FL_LD + c + 8];
            float inv = powf(10000.f, -(float)c / 8.f);
            float sn, cs;
            sincosf((float)(k0 + r) * inv, &sn, &cs);
            Ks[r * FL_LD + c]     = to_tf32(x1 * cs - x2 * sn);
            Ks[r * FL_LD + c + 8] = to_tf32(x2 * cs + x1 * sn);
        }
        for (int i = tid; i < 64 * 56; i += 128) {
            int r = i / 56, c = 16 + 2 * (i % 56);
            float2* p = (float2*)(Ks + r * FL_LD + c);
            float2 v = *p;
            v.x = to_tf32(v.x); v.y = to_tf32(v.y);
            *p = v;
        }
        for (int i = tid; i < 64 * 64; i += 128) {
            int r = i >> 6, c = 2 * (i & 63);
            float2* p = (float2*)(Vs + r * FL_LD + c);
            float2 v = *p;
            v.x = to_tf32(v.x); v.y = to_tf32(v.y);
            *p = v;
        }
        __syncthreads();

        if (k0 <= q0 + wm + 15) {
            float s[8][4];
#pragma unroll
            for (int nt = 0; nt < 8; nt++)
#pragma unroll
                for (int v = 0; v < 4; v++) s[nt][v] = 0.f;
#pragma unroll
            for (int ks = 0; ks < 16; ks++) {
                int kd = ks * 8;
#pragma unroll
                for (int nt = 0; nt < 8; nt++) {
                    unsigned b0 = __float_as_uint(Ks[(8 * nt + g) * FL_LD + kd + tig]);
                    unsigned b1 = __float_as_uint(Ks[(8 * nt + g) * FL_LD + kd + tig + 4]);
                    mma8(s[nt], qf[ks][0], qf[ks][1], qf[ks][2], qf[ks][3], b0, b1);
                }
            }
#pragma unroll
            for (int nt = 0; nt < 8; nt++) {
                int c0 = k0 + 8 * nt + 2 * tig;
                int c1 = c0 + 1;
                if (c0 > r0) s[nt][0] = -1e30f;
                if (c1 > r0) s[nt][1] = -1e30f;
                if (c0 > r1) s[nt][2] = -1e30f;
                if (c1 > r1) s[nt][3] = -1e30f;
            }
            float mx0 = -1e30f, mx1 = -1e30f;
#pragma unroll
            for (int nt = 0; nt < 8; nt++) {
                mx0 = fmaxf(mx0, fmaxf(s[nt][0], s[nt][1]));
                mx1 = fmaxf(mx1, fmaxf(s[nt][2], s[nt][3]));
            }
            mx0 = fmaxf(mx0, __shfl_xor_sync(FULL, mx0, 1));
            mx0 = fmaxf(mx0, __shfl_xor_sync(FULL, mx0, 2));
            mx1 = fmaxf(mx1, __shfl_xor_sync(FULL, mx1, 1));
            mx1 = fmaxf(mx1, __shfl_xor_sync(FULL, mx1, 2));
            float mn0 = fmaxf(mrow0, mx0);
            float mn1 = fmaxf(mrow1, mx1);
            float al0 = __expf(mrow0 - mn0);
            float al1 = __expf(mrow1 - mn1);
            mrow0 = mn0; mrow1 = mn1;
            float sum0 = 0.f, sum1 = 0.f;
#pragma unroll
            for (int nt = 0; nt < 8; nt++) {
                s[nt][0] = __expf(s[nt][0] - mn0);
                s[nt][1] = __expf(s[nt][1] - mn0);
                s[nt][2] = __expf(s[nt][2] - mn1);
                s[nt][3] = __expf(s[nt][3] - mn1);
                sum0 += s[nt][0] + s[nt][1];
                sum1 += s[nt][2] + s[nt][3];
            }
            sum0 += __shfl_xor_sync(FULL, sum0, 1);
            sum0 += __shfl_xor_sync(FULL, sum0, 2);
            sum1 += __shfl_xor_sync(FULL, sum1, 1);
            sum1 += __shfl_xor_sync(FULL, sum1, 2);
            lrow0 = lrow0 * al0 + sum0;
            lrow1 = lrow1 * al1 + sum1;
#pragma unroll
            for (int nto = 0; nto < 16; nto++) {
                acc_o[nto][0] *= al0; acc_o[nto][1] *= al0;
                acc_o[nto][2] *= al1; acc_o[nto][3] *= al1;
            }
            int src0 = (lane & ~3) | (tig >> 1);
            int src1 = src0 + 2;
            int sel = tig & 1;
#pragma unroll
            for (int kk = 0; kk < 8; kk++) {
                float x0 = __shfl_sync(FULL, s[kk][0], src0);
                float x1 = __shfl_sync(FULL, s[kk][1], src0);
                float x2 = __shfl_sync(FULL, s[kk][2], src0);
                float x3 = __shfl_sync(FULL, s[kk][3], src0);
                float y0 = __shfl_sync(FULL, s[kk][0], src1);
                float y1 = __shfl_sync(FULL, s[kk][1], src1);
                float y2 = __shfl_sync(FULL, s[kk][2], src1);
                float y3 = __shfl_sync(FULL, s[kk][3], src1);
                unsigned a0 = __float_as_uint(to_tf32(sel ? x1 : x0));
                unsigned a1 = __float_as_uint(to_tf32(sel ? x3 : x2));
                unsigned a2 = __float_as_uint(to_tf32(sel ? y1 : y0));
                unsigned a3 = __float_as_uint(to_tf32(sel ? y3 : y2));
#pragma unroll
                for (int nto = 0; nto < 16; nto++) {
                    unsigned b0 = __float_as_uint(Vs[(8 * kk + tig) * FL_LD + 8 * nto + g]);
                    unsigned b1 = __float_as_uint(Vs[(8 * kk + tig + 4) * FL_LD + 8 * nto + g]);
                    mma8(acc_o[nto], a0, a1, a2, a3, b0, b1);
                }
            }
        }
    }

    float inv0 = 1.f / lrow0;
    float inv1 = 1.f / lrow1;
    int b = bh >> 4, h = bh & 15;
    float* y0 = g_Y + ((long)(b * T_SEQ + r0)) * DIMC + h * HD;
    float* y1 = g_Y + ((long)(b * T_SEQ + r1)) * DIMC + h * HD;
#pragma unroll
    for (int nto = 0; nto < 16; nto++) {
        int d = 8 * nto + 2 * tig;
        *(float2*)(y0 + d) = make_float2(to_tf32(acc_o[nto][0] * inv0),
                                         to_tf32(acc_o[nto][1] * inv0));
        *(float2*)(y1 + d) = make_float2(to_tf32(acc_o[nto][2] * inv1),
                                         to_tf32(acc_o[nto][3] * inv1));
    }
}

// ---------------------------------------------------------------------------
extern "C" void kernel_launch(void* const* d_in, const int* in_sizes, int n_in,
                              void* d_out, int out_size)
{
    const float* x    = (const float*)d_in[0];
    const float* Wqkv = (const float*)d_in[1];
    const float* Wout = (const float*)d_in[2];
    float* out = (float*)d_out;

    static int attr_done = 0;
    if (!attr_done) {
        cudaFuncSetAttribute(gemm_mma_kernel<0>,
                             cudaFuncAttributeMaxDynamicSharedMemorySize, GEMM_SMEM);
        cudaFuncSetAttribute(gemm_mma_kernel<1>,
                             cudaFuncAttributeMaxDynamicSharedMemorySize, GEMM_SMEM);
        cudaFuncSetAttribute(flash_mma_kernel,
                             cudaFuncAttributeMaxDynamicSharedMemorySize, FLASH_SMEM);
        attr_done = 1;
    }

    // 0) fused pre-pass (round x + both weight transposes)
    prep_kernel<<<NXB + NQB + NOB, 256>>>(x, Wqkv, Wout);
    // 1) QKV projection -> g_Q/g_K/g_V
    {
        dim3 grid(N_QKV / 128, NTOK / 128);   // 48 x 64
        gemm_mma_kernel<0><<<grid, 512, GEMM_SMEM>>>(nullptr, N_QKV);
    }
    // 2) flash attention (rope fused, Q in regs) -> g_Y
    {
        dim3 grid(T_SEQ / 64, BH);            // 8 x 256
        flash_mma_kernel<<<grid, 128, FLASH_SMEM>>>();
    }
    // 3) output projection
    {
        dim3 grid(DIMC / 128, NTOK / 128);    // 16 x 64
        gemm_mma_kernel<1><<<grid, 512, GEMM_SMEM>>>(out, DIMC);
    }
}

// round 14
// speedup vs baseline: 1.0901x; 1.0901x over previous
#include <cuda_runtime.h>
#include <math.h>

#define DIMC   2048
#define NH     16
#define HD     128
#define T_SEQ  512
#define BATCH  16
#define BH     (BATCH * NH)      // 256
#define NTOK   (BATCH * T_SEQ)   // 8192
#define N_QKV  (3 * DIMC)        // 6144
#define GKD    2048

// Scratch (device globals; no allocations allowed)
__device__ float g_Q[BH * T_SEQ * HD];
__device__ float g_K[BH * T_SEQ * HD];
__device__ float g_V[BH * T_SEQ * HD];
__device__ float g_Y[NTOK * DIMC];        // attention out, tf32-rounded
__device__ float g_xr[NTOK * DIMC];       // x, tf32-rounded
__device__ float g_WqkvT[N_QKV * DIMC];   // [6144][2048], tf32-rounded
__device__ float g_WoutT[DIMC * DIMC];    // [2048][2048], tf32-rounded

// ---------------------------------------------------------------------------
__device__ __forceinline__ float to_tf32(float x) {
    float y;
    asm("cvt.rna.tf32.f32 %0, %1;" : "=f"(y) : "f"(x));
    return y;
}
__device__ __forceinline__ unsigned smem_u32(const void* p) {
    unsigned a;
    asm("{ .reg .u64 t; cvta.to.shared.u64 t, %1; cvt.u32.u64 %0, t; }"
        : "=r"(a) : "l"(p));
    return a;
}
__device__ __forceinline__ void mma8(float* c,
                                     unsigned a0, unsigned a1, unsigned a2, unsigned a3,
                                     unsigned b0, unsigned b1) {
    asm volatile(
        "mma.sync.aligned.m16n8k8.row.col.f32.tf32.tf32.f32 "
        "{%0,%1,%2,%3}, {%4,%5,%6,%7}, {%8,%9}, {%0,%1,%2,%3};"
        : "+f"(c[0]), "+f"(c[1]), "+f"(c[2]), "+f"(c[3])
        : "r"(a0), "r"(a1), "r"(a2), "r"(a3), "r"(b0), "r"(b1));
}

// ---------------------------------------------------------------------------
// Fused pre-pass: round x + both weight transposes (one launch).
// ---------------------------------------------------------------------------
#define NXB (NTOK * DIMC / 4 / 256)       // 16384
#define NQB ((N_QKV / 32) * (DIMC / 32))  // 12288
#define NOB ((DIMC / 32) * (DIMC / 32))   // 4096

__global__ __launch_bounds__(256)
void prep_kernel(const float* __restrict__ x,
                 const float* __restrict__ Wqkv,
                 const float* __restrict__ Wout)
{
    __shared__ float t[32][33];
    int b = blockIdx.x;
    int tid = threadIdx.x;

    if (b < NXB) {
        long i = (long)b * 256 + tid;     // float4 index
        float4 v = *(const float4*)(x + i * 4);
        v.x = to_tf32(v.x); v.y = to_tf32(v.y);
        v.z = to_tf32(v.z); v.w = to_tf32(v.w);
        *(float4*)(g_xr + i * 4) = v;
        return;
    }

    const float* W;
    float* Wt;
    int N, bb;
    if (b < NXB + NQB) {
        bb = b - NXB; W = Wqkv; Wt = g_WqkvT; N = N_QKV;
    } else {
        bb = b - NXB - NQB; W = Wout; Wt = g_WoutT; N = DIMC;
    }
    int nblk = N / 32;
    int n0 = (bb % nblk) * 32, k0 = (bb / nblk) * 32;
    int tx = tid & 31, ty = tid >> 5;   // 32 x 8
#pragma unroll
    for (int i = 0; i < 32; i += 8)
        t[ty + i][tx] = to_tf32(W[(long)(k0 + ty + i) * N + n0 + tx]);
    __syncthreads();
#pragma unroll
    for (int i = 0; i < 32; i += 8)
        Wt[(long)(n0 + ty + i) * GKD + k0 + tx] = t[tx][ty + i];
}

// ---------------------------------------------------------------------------
// TF32 mma.sync GEMM: BM=128 BN=128 BK=32, 128 threads, 4 warps of 64x64
// warp tiles (2x2). 1.0 LDS/HMMA (smem-byte optimal), 3-stage cp.async,
// one __syncthreads per iter, 110KB smem -> 2 CTAs/SM.
// MODE 0: A=g_xr, B=g_WqkvT -> scatter g_Q/g_K/g_V ; MODE 1: A=g_Y -> out
// ---------------------------------------------------------------------------
#define BKP 36
#define TILE_F (128 * BKP)            // 4608 floats
#define STAGE_F (2 * TILE_F)          // 9216 floats
#define NSTAGE 3
#define GEMM_SMEM (NSTAGE * STAGE_F * 4)   // 110592 bytes

template <int MODE>
__global__ __launch_bounds__(128, 2)
void gemm_mma_kernel(float* __restrict__ Cmat, int N)
{
    extern __shared__ float sm[];

    const float* A  = (MODE == 0) ? g_xr : g_Y;
    const float* Bt = (MODE == 0) ? g_WqkvT : g_WoutT;

    int tid = threadIdx.x;
    int wid = tid >> 5;
    int lane = tid & 31;
    int g = lane >> 2;
    int tig = lane & 3;

    int bm = blockIdx.y * 128;
    int bn = blockIdx.x * 128;
    int wm = (wid & 1) * 64;      // 2 warp rows
    int wn = (wid >> 1) * 64;     // 2 warp cols

    const float* Arow = A + (long)bm * GKD;
    const float* Brow = Bt + (long)bn * GKD;

    float acc[4][8][4];
#pragma unroll
    for (int mt = 0; mt < 4; mt++)
#pragma unroll
        for (int nt = 0; nt < 8; nt++)
#pragma unroll
            for (int v = 0; v < 4; v++) acc[mt][nt][v] = 0.f;

    auto load_stage = [&](int it, int st) {
        float* dstA = sm + st * STAGE_F;
        float* dstB = dstA + TILE_F;
        int k0 = it * 32;
#pragma unroll
        for (int i = 0; i < 8; i++) {
            int id = tid + 128 * i;          // 0..1023
            int r = id >> 3, ch = id & 7;
            unsigned da = smem_u32(dstA + r * BKP + ch * 4);
            const float* sa = Arow + (long)r * GKD + k0 + ch * 4;
            asm volatile("cp.async.cg.shared.global [%0], [%1], 16;"
                         :: "r"(da), "l"(sa));
            unsigned db = smem_u32(dstB + r * BKP + ch * 4);
            const float* sb = Brow + (long)r * GKD + k0 + ch * 4;
            asm volatile("cp.async.cg.shared.global [%0], [%1], 16;"
                         :: "r"(db), "l"(sb));
        }
        asm volatile("cp.async.commit_group;" ::: "memory");
    };

    auto compute = [&](const float* s) {
        const float* As = s;
        const float* Bs = s + TILE_F;
#pragma unroll
        for (int ks = 0; ks < 32; ks += 8) {
            unsigned a[4][4];
#pragma unroll
            for (int mt = 0; mt < 4; mt++) {
                int r = wm + 16 * mt + g;
                a[mt][0] = __float_as_uint(As[r * BKP + ks + tig]);
                a[mt][1] = __float_as_uint(As[(r + 8) * BKP + ks + tig]);
                a[mt][2] = __float_as_uint(As[r * BKP + ks + tig + 4]);
                a[mt][3] = __float_as_uint(As[(r + 8) * BKP + ks + tig + 4]);
            }
#pragma unroll
            for (int nt = 0; nt < 8; nt++) {
                int rn = wn + 8 * nt + g;
                unsigned b0 = __float_as_uint(Bs[rn * BKP + ks + tig]);
                unsigned b1 = __float_as_uint(Bs[rn * BKP + ks + tig + 4]);
#pragma unroll
                for (int mt = 0; mt < 4; mt++)
                    mma8(acc[mt][nt], a[mt][0], a[mt][1], a[mt][2], a[mt][3], b0, b1);
            }
        }
    };

    const int NIT = GKD / 32;     // 64
    load_stage(0, 0);
    load_stage(1, 1);

    for (int it = 0; it < NIT; it++) {
        if (it < NIT - 1)
            asm volatile("cp.async.wait_group 1;" ::: "memory");
        else
            asm volatile("cp.async.wait_group 0;" ::: "memory");
        __syncthreads();
        if (it + 2 < NIT) load_stage(it + 2, (it + 2) % NSTAGE);
        compute(sm + (it % NSTAGE) * STAGE_F);
    }

    // epilogue
#pragma unroll
    for (int mt = 0; mt < 4; mt++) {
#pragma unroll
        for (int nt = 0; nt < 8; nt++) {
            int col = bn + wn + 8 * nt + 2 * tig;
#pragma unroll
            for (int half = 0; half < 2; half++) {
                int m = bm + wm + 16 * mt + g + 8 * half;
                float2 v = make_float2(acc[mt][nt][2 * half],
                                       acc[mt][nt][2 * half + 1]);
                if (MODE == 0) {
                    int which = col >> 11;
                    int rm = col & 2047;
                    int h = rm >> 7, d = rm & 127;
                    float* dst = (which == 0) ? g_Q : (which == 1) ? g_K : g_V;
                    *(float2*)(dst + (((long)((m >> 9) * NH + h)) * T_SEQ
                                      + (m & 511)) * HD + d) = v;
                } else {
                    *(float2*)(Cmat + (long)m * N + col) = v;
                }
            }
        }
    }
}

// ---------------------------------------------------------------------------
// Flash v3 (unchanged from R12): Q in registers, 64-query CTAs of 128
// threads, single-buffered K/V smem (69.6 KB -> 2 CTAs/SM), causal tf32 mma.
// ---------------------------------------------------------------------------
#define FL_LD 136
#define FLASH_SMEM (2 * 64 * FL_LD * 4)   // 69632 B

__global__ __launch_bounds__(128)
void flash_mma_kernel()
{
    extern __shared__ float fsm[];
    float* Ks = fsm;                     // [64][FL_LD]
    float* Vs = fsm + 64 * FL_LD;        // [64][FL_LD]

    int bh = blockIdx.y;
    int q0 = blockIdx.x * 64;
    int tid = threadIdx.x;
    int wid = tid >> 5;
    int lane = tid & 31;
    int g = lane >> 2;
    int tig = lane & 3;
    int wm = wid * 16;

    const float* Qg = g_Q + (long)bh * T_SEQ * HD;
    const float* Kg = g_K + (long)bh * T_SEQ * HD;
    const float* Vg = g_V + (long)bh * T_SEQ * HD;

    const float scale = 0.08838834764831845f;
    const unsigned FULL = 0xffffffffu;

    int r0 = q0 + wm + g;
    int r1 = r0 + 8;

    // ---- load Q fragments, rope in-register, scale+round ----
    float qv[16][4];
#pragma unroll
    for (int ks = 0; ks < 16; ks++) {
        qv[ks][0] = Qg[(long)r0 * HD + 8 * ks + tig];
        qv[ks][1] = Qg[(long)r1 * HD + 8 * ks + tig];
        qv[ks][2] = Qg[(long)r0 * HD + 8 * ks + tig + 4];
        qv[ks][3] = Qg[(long)r1 * HD + 8 * ks + tig + 4];
    }
#pragma unroll
    for (int j = 0; j < 4; j++) {
        int i = tig + ((j & 2) ? 4 : 0);
        int rr = (j & 1) ? r1 : r0;
        float inv = powf(10000.f, -(float)i / 8.f);
        float sn, cs;
        sincosf((float)rr * inv, &sn, &cs);
        float x1 = qv[0][j], x2 = qv[1][j];
        qv[0][j] = x1 * cs - x2 * sn;
        qv[1][j] = x2 * cs + x1 * sn;
    }
    unsigned qf[16][4];
#pragma unroll
    for (int ks = 0; ks < 16; ks++)
#pragma unroll
        for (int j = 0; j < 4; j++)
            qf[ks][j] = __float_as_uint(to_tf32(qv[ks][j] * scale));

    float acc_o[16][4];
#pragma unroll
    for (int nto = 0; nto < 16; nto++)
#pragma unroll
        for (int v = 0; v < 4; v++) acc_o[nto][v] = 0.f;
    float mrow0 = -1e30f, mrow1 = -1e30f;
    float lrow0 = 0.f, lrow1 = 0.f;

    int nkt = q0 / 64 + 1;

    for (int kt = 0; kt < nkt; kt++) {
        int k0 = kt * 64;
        __syncthreads();
        {
            const float* ks = Kg + (long)k0 * HD;
            const float* vs = Vg + (long)k0 * HD;
#pragma unroll
            for (int i = tid; i < 2048; i += 128) {
                int r = i >> 5, ch = i & 31;
                unsigned dk = smem_u32(Ks + r * FL_LD + ch * 4);
                asm volatile("cp.async.cg.shared.global [%0], [%1], 16;"
                             :: "r"(dk), "l"(ks + (long)r * HD + ch * 4));
                unsigned dv = smem_u32(Vs + r * FL_LD + ch * 4);
                asm volatile("cp.async.cg.shared.global [%0], [%1], 16;"
                             :: "r"(dv), "l"(vs + (long)r * HD + ch * 4));
            }
            asm volatile("cp.async.commit_group;" ::: "memory");
            asm volatile("cp.async.wait_group 0;" ::: "memory");
        }
        __syncthreads();
        for (int i = tid; i < 512; i += 128) {
            int r = i >> 3, c = i & 7;
            float x1 = Ks[r * FL_LD + c], x2 = Ks[r * FL_LD + c + 8];
            float inv = powf(10000.f, -(float)c / 8.f);
            float sn, cs;
            sincosf((float)(k0 + r) * inv, &sn, &cs);
            Ks[r * FL_LD + c]     = to_tf32(x1 * cs - x2 * sn);
            Ks[r * FL_LD + c + 8] = to_tf32(x2 * cs + x1 * sn);
        }
        for (int i = tid; i < 64 * 56; i += 128) {
            int r = i / 56, c = 16 + 2 * (i % 56);
            float2* p = (float2*)(Ks + r * FL_LD + c);
            float2 v = *p;
            v.x = to_tf32(v.x); v.y = to_tf32(v.y);
            *p = v;
        }
        for (int i = tid; i < 64 * 64; i += 128) {
            int r = i >> 6, c = 2 * (i & 63);
            float2* p = (float2*)(Vs + r * FL_LD + c);
            float2 v = *p;
            v.x = to_tf32(v.x); v.y = to_tf32(v.y);
            *p = v;
        }
        __syncthreads();

        if (k0 <= q0 + wm + 15) {
            float s[8][4];
#pragma unroll
            for (int nt = 0; nt < 8; nt++)
#pragma unroll
                for (int v = 0; v < 4; v++) s[nt][v] = 0.f;
#pragma unroll
            for (int ks = 0; ks < 16; ks++) {
                int kd = ks * 8;
#pragma unroll
                for (int nt = 0; nt < 8; nt++) {
                    unsigned b0 = __float_as_uint(Ks[(8 * nt + g) * FL_LD + kd + tig]);
                    unsigned b1 = __float_as_uint(Ks[(8 * nt + g) * FL_LD + kd + tig + 4]);
                    mma8(s[nt], qf[ks][0], qf[ks][1], qf[ks][2], qf[ks][3], b0, b1);
                }
            }
#pragma unroll
            for (int nt = 0; nt < 8; nt++) {
                int c0 = k0 + 8 * nt + 2 * tig;
                int c1 = c0 + 1;
                if (c0 > r0) s[nt][0] = -1e30f;
                if (c1 > r0) s[nt][1] = -1e30f;
                if (c0 > r1) s[nt][2] = -1e30f;
                if (c1 > r1) s[nt][3] = -1e30f;
            }
            float mx0 = -1e30f, mx1 = -1e30f;
#pragma unroll
            for (int nt = 0; nt < 8; nt++) {
                mx0 = fmaxf(mx0, fmaxf(s[nt][0], s[nt][1]));
                mx1 = fmaxf(mx1, fmaxf(s[nt][2], s[nt][3]));
            }
            mx0 = fmaxf(mx0, __shfl_xor_sync(FULL, mx0, 1));
            mx0 = fmaxf(mx0, __shfl_xor_sync(FULL, mx0, 2));
            mx1 = fmaxf(mx1, __shfl_xor_sync(FULL, mx1, 1));
            mx1 = fmaxf(mx1, __shfl_xor_sync(FULL, mx1, 2));
            float mn0 = fmaxf(mrow0, mx0);
            float mn1 = fmaxf(mrow1, mx1);
            float al0 = __expf(mrow0 - mn0);
            float al1 = __expf(mrow1 - mn1);
            mrow0 = mn0; mrow1 = mn1;
            float sum0 = 0.f, sum1 = 0.f;
#pragma unroll
            for (int nt = 0; nt < 8; nt++) {
                s[nt][0] = __expf(s[nt][0] - mn0);
                s[nt][1] = __expf(s[nt][1] - mn0);
                s[nt][2] = __expf(s[nt][2] - mn1);
                s[nt][3] = __expf(s[nt][3] - mn1);
                sum0 += s[nt][0] + s[nt][1];
                sum1 += s[nt][2] + s[nt][3];
            }
            sum0 += __shfl_xor_sync(FULL, sum0, 1);
            sum0 += __shfl_xor_sync(FULL, sum0, 2);
            sum1 += __shfl_xor_sync(FULL, sum1, 1);
            sum1 += __shfl_xor_sync(FULL, sum1, 2);
            lrow0 = lrow0 * al0 + sum0;
            lrow1 = lrow1 * al1 + sum1;
#pragma unroll
            for (int nto = 0; nto < 16; nto++) {
                acc_o[nto][0] *= al0; acc_o[nto][1] *= al0;
                acc_o[nto][2] *= al1; acc_o[nto][3] *= al1;
            }
            int src0 = (lane & ~3) | (tig >> 1);
            int src1 = src0 + 2;
            int sel = tig & 1;
#pragma unroll
            for (int kk = 0; kk < 8; kk++) {
                float x0 = __shfl_sync(FULL, s[kk][0], src0);
                float x1 = __shfl_sync(FULL, s[kk][1], src0);
                float x2 = __shfl_sync(FULL, s[kk][2], src0);
                float x3 = __shfl_sync(FULL, s[kk][3], src0);
                float y0 = __shfl_sync(FULL, s[kk][0], src1);
                float y1 = __shfl_sync(FULL, s[kk][1], src1);
                float y2 = __shfl_sync(FULL, s[kk][2], src1);
                float y3 = __shfl_sync(FULL, s[kk][3], src1);
                unsigned a0 = __float_as_uint(to_tf32(sel ? x1 : x0));
                unsigned a1 = __float_as_uint(to_tf32(sel ? x3 : x2));
                unsigned a2 = __float_as_uint(to_tf32(sel ? y1 : y0));
                unsigned a3 = __float_as_uint(to_tf32(sel ? y3 : y2));
#pragma unroll
                for (int nto = 0; nto < 16; nto++) {
                    unsigned b0 = __float_as_uint(Vs[(8 * kk + tig) * FL_LD + 8 * nto + g]);
                    unsigned b1 = __float_as_uint(Vs[(8 * kk + tig + 4) * FL_LD + 8 * nto + g]);
                    mma8(acc_o[nto], a0, a1, a2, a3, b0, b1);
                }
            }
        }
    }

    float inv0 = 1.f / lrow0;
    float inv1 = 1.f / lrow1;
    int b = bh >> 4, h = bh & 15;
    float* y0 = g_Y + ((long)(b * T_SEQ + r0)) * DIMC + h * HD;
    float* y1 = g_Y + ((long)(b * T_SEQ + r1)) * DIMC + h * HD;
#pragma unroll
    for (int nto = 0; nto < 16; nto++) {
        int d = 8 * nto + 2 * tig;
        *(float2*)(y0 + d) = make_float2(to_tf32(acc_o[nto][0] * inv0),
                                         to_tf32(acc_o[nto][1] * inv0));
        *(float2*)(y1 + d) = make_float2(to_tf32(acc_o[nto][2] * inv1),
                                         to_tf32(acc_o[nto][3] * inv1));
    }
}

// ---------------------------------------------------------------------------
extern "C" void kernel_launch(void* const* d_in, const int* in_sizes, int n_in,
                              void* d_out, int out_size)
{
    const float* x    = (const float*)d_in[0];
    const float* Wqkv = (const float*)d_in[1];
    const float* Wout = (const float*)d_in[2];
    float* out = (float*)d_out;

    static int attr_done = 0;
    if (!attr_done) {
        cudaFuncSetAttribute(gemm_mma_kernel<0>,
                             cudaFuncAttributeMaxDynamicSharedMemorySize, GEMM_SMEM);
        cudaFuncSetAttribute(gemm_mma_kernel<1>,
                             cudaFuncAttributeMaxDynamicSharedMemorySize, GEMM_SMEM);
        cudaFuncSetAttribute(flash_mma_kernel,
                             cudaFuncAttributeMaxDynamicSharedMemorySize, FLASH_SMEM);
        attr_done = 1;
    }

    // 0) fused pre-pass (round x + both weight transposes)
    prep_kernel<<<NXB + NQB + NOB, 256>>>(x, Wqkv, Wout);
    // 1) QKV projection -> g_Q/g_K/g_V
    {
        dim3 grid(N_QKV / 128, NTOK / 128);   // 48 x 64
        gemm_mma_kernel<0><<<grid, 128, GEMM_SMEM>>>(nullptr, N_QKV);
    }
    // 2) flash attention (rope fused, Q in regs) -> g_Y
    {
        dim3 grid(T_SEQ / 64, BH);            // 8 x 256
        flash_mma_kernel<<<grid, 128, FLASH_SMEM>>>();
    }
    // 3) output projection
    {
        dim3 grid(DIMC / 128, NTOK / 128);    // 16 x 64
        gemm_mma_kernel<1><<<grid, 128, GEMM_SMEM>>>(out, DIMC);
    }
}

// round 17
// speedup vs baseline: 1.1435x; 1.0490x over previous
#include <cuda_runtime.h>
#include <math.h>

#define DIMC   2048
#define NH     16
#define HD     128
#define T_SEQ  512
#define BATCH  16
#define BH     (BATCH * NH)      // 256
#define NTOK   (BATCH * T_SEQ)   // 8192
#define N_QKV  (3 * DIMC)        // 6144
#define GKD    2048

// Scratch (device globals; no allocations allowed)
__device__ float g_Q[BH * T_SEQ * HD];    // tf32-rounded at GEMM epilogue
__device__ float g_K[BH * T_SEQ * HD];    // tf32-rounded
__device__ float g_V[BH * T_SEQ * HD];    // tf32-rounded
__device__ float g_Y[NTOK * DIMC];        // attention out, tf32-rounded
__device__ float g_xr[NTOK * DIMC];       // x, tf32-rounded
__device__ float g_WqkvT[N_QKV * DIMC];   // [6144][2048], tf32-rounded
__device__ float g_WoutT[DIMC * DIMC];    // [2048][2048], tf32-rounded

// ---------------------------------------------------------------------------
__device__ __forceinline__ float to_tf32(float x) {
    float y;
    asm("cvt.rna.tf32.f32 %0, %1;" : "=f"(y) : "f"(x));
    return y;
}
__device__ __forceinline__ unsigned smem_u32(const void* p) {
    unsigned a;
    asm("{ .reg .u64 t; cvta.to.shared.u64 t, %1; cvt.u32.u64 %0, t; }"
        : "=r"(a) : "l"(p));
    return a;
}
__device__ __forceinline__ void mma8(float* c,
                                     unsigned a0, unsigned a1, unsigned a2, unsigned a3,
                                     unsigned b0, unsigned b1) {
    asm volatile(
        "mma.sync.aligned.m16n8k8.row.col.f32.tf32.tf32.f32 "
        "{%0,%1,%2,%3}, {%4,%5,%6,%7}, {%8,%9}, {%0,%1,%2,%3};"
        : "+f"(c[0]), "+f"(c[1]), "+f"(c[2]), "+f"(c[3])
        : "r"(a0), "r"(a1), "r"(a2), "r"(a3), "r"(b0), "r"(b1));
}

// ---------------------------------------------------------------------------
// Fused pre-pass: round x + both weight transposes (one launch).
// ---------------------------------------------------------------------------
#define NXB (NTOK * DIMC / 4 / 256)       // 16384
#define NQB ((N_QKV / 32) * (DIMC / 32))  // 12288
#define NOB ((DIMC / 32) * (DIMC / 32))   // 4096

__global__ __launch_bounds__(256)
void prep_kernel(const float* __restrict__ x,
                 const float* __restrict__ Wqkv,
                 const float* __restrict__ Wout)
{
    __shared__ float t[32][33];
    int b = blockIdx.x;
    int tid = threadIdx.x;

    if (b < NXB) {
        long i = (long)b * 256 + tid;     // float4 index
        float4 v = *(const float4*)(x + i * 4);
        v.x = to_tf32(v.x); v.y = to_tf32(v.y);
        v.z = to_tf32(v.z); v.w = to_tf32(v.w);
        *(float4*)(g_xr + i * 4) = v;
        return;
    }

    const float* W;
    float* Wt;
    int N, bb;
    if (b < NXB + NQB) {
        bb = b - NXB; W = Wqkv; Wt = g_WqkvT; N = N_QKV;
    } else {
        bb = b - NXB - NQB; W = Wout; Wt = g_WoutT; N = DIMC;
    }
    int nblk = N / 32;
    int n0 = (bb % nblk) * 32, k0 = (bb / nblk) * 32;
    int tx = tid & 31, ty = tid >> 5;   // 32 x 8
#pragma unroll
    for (int i = 0; i < 32; i += 8)
        t[ty + i][tx] = to_tf32(W[(long)(k0 + ty + i) * N + n0 + tx]);
    __syncthreads();
#pragma unroll
    for (int i = 0; i < 32; i += 8)
        Wt[(long)(n0 + ty + i) * GKD + k0 + tx] = t[tx][ty + i];
}

// ---------------------------------------------------------------------------
// TF32 mma.sync GEMM (R12 proven-best config): BM=128 BN=128 BK=32, 256 thr,
// 8 warps of 32x64, 3-stage cp.async, one sync/iter, scalar LDS frags.
// MODE 0: A=g_xr, B=g_WqkvT -> scatter g_Q/g_K/g_V (tf32-ROUNDED stores)
// MODE 1: A=g_Y,  B=g_WoutT -> out (exact fp32 stores)
// ---------------------------------------------------------------------------
#define BKP 36
#define TILE_F (128 * BKP)            // 4608 floats
#define STAGE_F (2 * TILE_F)          // 9216 floats
#define NSTAGE 3
#define GEMM_SMEM (NSTAGE * STAGE_F * 4)   // 110592 bytes

template <int MODE>
__global__ __launch_bounds__(256, 2)
void gemm_mma_kernel(float* __restrict__ Cmat, int N)
{
    extern __shared__ float sm[];

    const float* A  = (MODE == 0) ? g_xr : g_Y;
    const float* Bt = (MODE == 0) ? g_WqkvT : g_WoutT;

    int tid = threadIdx.x;
    int wid = tid >> 5;
    int lane = tid & 31;
    int g = lane >> 2;
    int tig = lane & 3;

    int bm = blockIdx.y * 128;
    int bn = blockIdx.x * 128;
    int wm = (wid & 3) * 32;
    int wn = (wid >> 2) * 64;

    const float* Arow = A + (long)bm * GKD;
    const float* Brow = Bt + (long)bn * GKD;

    float acc[2][8][4];
#pragma unroll
    for (int mt = 0; mt < 2; mt++)
#pragma unroll
        for (int nt = 0; nt < 8; nt++)
#pragma unroll
            for (int v = 0; v < 4; v++) acc[mt][nt][v] = 0.f;

    auto load_stage = [&](int it, int st) {
        float* dstA = sm + st * STAGE_F;
        float* dstB = dstA + TILE_F;
        int k0 = it * 32;
#pragma unroll
        for (int i = 0; i < 4; i++) {
            int id = tid + 256 * i;          // 0..1023
            int r = id >> 3, ch = id & 7;
            unsigned da = smem_u32(dstA + r * BKP + ch * 4);
            const float* sa = Arow + (long)r * GKD + k0 + ch * 4;
            asm volatile("cp.async.cg.shared.global [%0], [%1], 16;"
                         :: "r"(da), "l"(sa));
            unsigned db = smem_u32(dstB + r * BKP + ch * 4);
            const float* sb = Brow + (long)r * GKD + k0 + ch * 4;
            asm volatile("cp.async.cg.shared.global [%0], [%1], 16;"
                         :: "r"(db), "l"(sb));
        }
        asm volatile("cp.async.commit_group;" ::: "memory");
    };

    auto compute = [&](const float* s) {
        const float* As = s;
        const float* Bs = s + TILE_F;
#pragma unroll
        for (int ks = 0; ks < 32; ks += 8) {
            unsigned a[2][4];
#pragma unroll
            for (int mt = 0; mt < 2; mt++) {
                int r = wm + 16 * mt + g;
                a[mt][0] = __float_as_uint(As[r * BKP + ks + tig]);
                a[mt][1] = __float_as_uint(As[(r + 8) * BKP + ks + tig]);
                a[mt][2] = __float_as_uint(As[r * BKP + ks + tig + 4]);
                a[mt][3] = __float_as_uint(As[(r + 8) * BKP + ks + tig + 4]);
            }
#pragma unroll
            for (int nt = 0; nt < 8; nt++) {
                int rn = wn + 8 * nt + g;
                unsigned b0 = __float_as_uint(Bs[rn * BKP + ks + tig]);
                unsigned b1 = __float_as_uint(Bs[rn * BKP + ks + tig + 4]);
#pragma unroll
                for (int mt = 0; mt < 2; mt++)
                    mma8(acc[mt][nt], a[mt][0], a[mt][1], a[mt][2], a[mt][3], b0, b1);
            }
        }
    };

    const int NIT = GKD / 32;     // 64
    load_stage(0, 0);
    load_stage(1, 1);

    for (int it = 0; it < NIT; it++) {
        if (it < NIT - 1)
            asm volatile("cp.async.wait_group 1;" ::: "memory");
        else
            asm volatile("cp.async.wait_group 0;" ::: "memory");
        __syncthreads();
        if (it + 2 < NIT) load_stage(it + 2, (it + 2) % NSTAGE);
        compute(sm + (it % NSTAGE) * STAGE_F);
    }

    // epilogue
#pragma unroll
    for (int mt = 0; mt < 2; mt++) {
#pragma unroll
        for (int nt = 0; nt < 8; nt++) {
            int col = bn + wn + 8 * nt + 2 * tig;
#pragma unroll
            for (int half = 0; half < 2; half++) {
                int m = bm + wm + 16 * mt + g + 8 * half;
                if (MODE == 0) {
                    // round to tf32 at store: flash consumes operands directly
                    float2 v = make_float2(to_tf32(acc[mt][nt][2 * half]),
                                           to_tf32(acc[mt][nt][2 * half + 1]));
                    int which = col >> 11;
                    int rm = col & 2047;
                    int h = rm >> 7, d = rm & 127;
                    float* dst = (which == 0) ? g_Q : (which == 1) ? g_K : g_V;
                    *(float2*)(dst + (((long)((m >> 9) * NH + h)) * T_SEQ
                                      + (m & 511)) * HD + d) = v;
                } else {
                    float2 v = make_float2(acc[mt][nt][2 * half],
                                           acc[mt][nt][2 * half + 1]);
                    *(float2*)(Cmat + (long)m * N + col) = v;
                }
            }
        }
    }
}

// ---------------------------------------------------------------------------
// Flash v4: Q in registers, 64-query CTAs of 128 threads, single-buffered
// K/V smem (2 CTAs/SM). K/V arrive PRE-ROUNDED from gemm<0> -> only the
// 16 rope dims of K need in-smem conversion. Causal, tf32 mma.
// ---------------------------------------------------------------------------
#define FL_LD 136
#define FLASH_SMEM (2 * 64 * FL_LD * 4)   // 69632 B

__global__ __launch_bounds__(128)
void flash_mma_kernel()
{
    extern __shared__ float fsm[];
    float* Ks = fsm;                     // [64][FL_LD]
    float* Vs = fsm + 64 * FL_LD;        // [64][FL_LD]

    int bh = blockIdx.y;
    int q0 = blockIdx.x * 64;
    int tid = threadIdx.x;
    int wid = tid >> 5;
    int lane = tid & 31;
    int g = lane >> 2;
    int tig = lane & 3;
    int wm = wid * 16;

    const float* Qg = g_Q + (long)bh * T_SEQ * HD;
    const float* Kg = g_K + (long)bh * T_SEQ * HD;
    const float* Vg = g_V + (long)bh * T_SEQ * HD;

    const float scale = 0.08838834764831845f;
    const unsigned FULL = 0xffffffffu;

    int r0 = q0 + wm + g;
    int r1 = r0 + 8;

    // ---- load Q fragments, rope in-register, scale+round ----
    float qv[16][4];
#pragma unroll
    for (int ks = 0; ks < 16; ks++) {
        qv[ks][0] = Qg[(long)r0 * HD + 8 * ks + tig];
        qv[ks][1] = Qg[(long)r1 * HD + 8 * ks + tig];
        qv[ks][2] = Qg[(long)r0 * HD + 8 * ks + tig + 4];
        qv[ks][3] = Qg[(long)r1 * HD + 8 * ks + tig + 4];
    }
#pragma unroll
    for (int j = 0; j < 4; j++) {
        int i = tig + ((j & 2) ? 4 : 0);
        int rr = (j & 1) ? r1 : r0;
        float inv = powf(10000.f, -(float)i / 8.f);
        float sn, cs;
        sincosf((float)rr * inv, &sn, &cs);
        float x1 = qv[0][j], x2 = qv[1][j];
        qv[0][j] = x1 * cs - x2 * sn;
        qv[1][j] = x2 * cs + x1 * sn;
    }
    unsigned qf[16][4];
#pragma unroll
    for (int ks = 0; ks < 16; ks++)
#pragma unroll
        for (int j = 0; j < 4; j++)
            qf[ks][j] = __float_as_uint(to_tf32(qv[ks][j] * scale));

    float acc_o[16][4];
#pragma unroll
    for (int nto = 0; nto < 16; nto++)
#pragma unroll
        for (int v = 0; v < 4; v++) acc_o[nto][v] = 0.f;
    float mrow0 = -1e30f, mrow1 = -1e30f;
    float lrow0 = 0.f, lrow1 = 0.f;

    int nkt = q0 / 64 + 1;

    for (int kt = 0; kt < nkt; kt++) {
        int k0 = kt * 64;
        __syncthreads();
        {
            const float* ks = Kg + (long)k0 * HD;
            const float* vs = Vg + (long)k0 * HD;
#pragma unroll
            for (int i = tid; i < 2048; i += 128) {
                int r = i >> 5, ch = i & 31;
                unsigned dk = smem_u32(Ks + r * FL_LD + ch * 4);
                asm volatile("cp.async.cg.shared.global [%0], [%1], 16;"
                             :: "r"(dk), "l"(ks + (long)r * HD + ch * 4));
                unsigned dv = smem_u32(Vs + r * FL_LD + ch * 4);
                asm volatile("cp.async.cg.shared.global [%0], [%1], 16;"
                             :: "r"(dv), "l"(vs + (long)r * HD + ch * 4));
            }
            asm volatile("cp.async.commit_group;" ::: "memory");
            asm volatile("cp.async.wait_group 0;" ::: "memory");
        }
        __syncthreads();
        // rope the first 16 dims of K (only conversion still needed)
        for (int i = tid; i < 512; i += 128) {
            int r = i >> 3, c = i & 7;
            float x1 = Ks[r * FL_LD + c], x2 = Ks[r * FL_LD + c + 8];
            float inv = powf(10000.f, -(float)c / 8.f);
            float sn, cs;
            sincosf((float)(k0 + r) * inv, &sn, &cs);
            Ks[r * FL_LD + c]     = to_tf32(x1 * cs - x2 * sn);
            Ks[r * FL_LD + c + 8] = to_tf32(x2 * cs + x1 * sn);
        }
        __syncthreads();

        if (k0 <= q0 + wm + 15) {
            float s[8][4];
#pragma unroll
            for (int nt = 0; nt < 8; nt++)
#pragma unroll
                for (int v = 0; v < 4; v++) s[nt][v] = 0.f;
#pragma unroll
            for (int ks = 0; ks < 16; ks++) {
                int kd = ks * 8;
#pragma unroll
                for (int nt = 0; nt < 8; nt++) {
                    unsigned b0 = __float_as_uint(Ks[(8 * nt + g) * FL_LD + kd + tig]);
                    unsigned b1 = __float_as_uint(Ks[(8 * nt + g) * FL_LD + kd + tig + 4]);
                    mma8(s[nt], qf[ks][0], qf[ks][1], qf[ks][2], qf[ks][3], b0, b1);
                }
            }
#pragma unroll
            for (int nt = 0; nt < 8; nt++) {
                int c0 = k0 + 8 * nt + 2 * tig;
                int c1 = c0 + 1;
                if (c0 > r0) s[nt][0] = -1e30f;
                if (c1 > r0) s[nt][1] = -1e30f;
                if (c0 > r1) s[nt][2] = -1e30f;
                if (c1 > r1) s[nt][3] = -1e30f;
            }
            float mx0 = -1e30f, mx1 = -1e30f;
#pragma unroll
            for (int nt = 0; nt < 8; nt++) {
                mx0 = fmaxf(mx0, fmaxf(s[nt][0], s[nt][1]));
                mx1 = fmaxf(mx1, fmaxf(s[nt][2], s[nt][3]));
            }
            mx0 = fmaxf(mx0, __shfl_xor_sync(FULL, mx0, 1));
            mx0 = fmaxf(mx0, __shfl_xor_sync(FULL, mx0, 2));
            mx1 = fmaxf(mx1, __shfl_xor_sync(FULL, mx1, 1));
            mx1 = fmaxf(mx1, __shfl_xor_sync(FULL, mx1, 2));
            float mn0 = fmaxf(mrow0, mx0);
            float mn1 = fmaxf(mrow1, mx1);
            float al0 = __expf(mrow0 - mn0);
            float al1 = __expf(mrow1 - mn1);
            mrow0 = mn0; mrow1 = mn1;
            float sum0 = 0.f, sum1 = 0.f;
#pragma unroll
            for (int nt = 0; nt < 8; nt++) {
                s[nt][0] = __expf(s[nt][0] - mn0);
                s[nt][1] = __expf(s[nt][1] - mn0);
                s[nt][2] = __expf(s[nt][2] - mn1);
                s[nt][3] = __expf(s[nt][3] - mn1);
                sum0 += s[nt][0] + s[nt][1];
                sum1 += s[nt][2] + s[nt][3];
            }
            sum0 += __shfl_xor_sync(FULL, sum0, 1);
            sum0 += __shfl_xor_sync(FULL, sum0, 2);
            sum1 += __shfl_xor_sync(FULL, sum1, 1);
            sum1 += __shfl_xor_sync(FULL, sum1, 2);
            lrow0 = lrow0 * al0 + sum0;
            lrow1 = lrow1 * al1 + sum1;
#pragma unroll
            for (int nto = 0; nto < 16; nto++) {
                acc_o[nto][0] *= al0; acc_o[nto][1] *= al0;
                acc_o[nto][2] *= al1; acc_o[nto][3] *= al1;
            }
            int src0 = (lane & ~3) | (tig >> 1);
            int src1 = src0 + 2;
            int sel = tig & 1;
#pragma unroll
            for (int kk = 0; kk < 8; kk++) {
                float x0 = __shfl_sync(FULL, s[kk][0], src0);
                float x1 = __shfl_sync(FULL, s[kk][1], src0);
                float x2 = __shfl_sync(FULL, s[kk][2], src0);
                float x3 = __shfl_sync(FULL, s[kk][3], src0);
                float y0 = __shfl_sync(FULL, s[kk][0], src1);
                float y1 = __shfl_sync(FULL, s[kk][1], src1);
                float y2 = __shfl_sync(FULL, s[kk][2], src1);
                float y3 = __shfl_sync(FULL, s[kk][3], src1);
                unsigned a0 = __float_as_uint(to_tf32(sel ? x1 : x0));
                unsigned a1 = __float_as_uint(to_tf32(sel ? x3 : x2));
                unsigned a2 = __float_as_uint(to_tf32(sel ? y1 : y0));
                unsigned a3 = __float_as_uint(to_tf32(sel ? y3 : y2));
#pragma unroll
                for (int nto = 0; nto < 16; nto++) {
                    unsigned b0 = __float_as_uint(Vs[(8 * kk + tig) * FL_LD + 8 * nto + g]);
                    unsigned b1 = __float_as_uint(Vs[(8 * kk + tig + 4) * FL_LD + 8 * nto + g]);
                    mma8(acc_o[nto], a0, a1, a2, a3, b0, b1);
                }
            }
        }
    }

    float inv0 = 1.f / lrow0;
    float inv1 = 1.f / lrow1;
    int b = bh >> 4, h = bh & 15;
    float* y0 = g_Y + ((long)(b * T_SEQ + r0)) * DIMC + h * HD;
    float* y1 = g_Y + ((long)(b * T_SEQ + r1)) * DIMC + h * HD;
#pragma unroll
    for (int nto = 0; nto < 16; nto++) {
        int d = 8 * nto + 2 * tig;
        *(float2*)(y0 + d) = make_float2(to_tf32(acc_o[nto][0] * inv0),
                                         to_tf32(acc_o[nto][1] * inv0));
        *(float2*)(y1 + d) = make_float2(to_tf32(acc_o[nto][2] * inv1),
                                         to_tf32(acc_o[nto][3] * inv1));
    }
}

// ---------------------------------------------------------------------------
extern "C" void kernel_launch(void* const* d_in, const int* in_sizes, int n_in,
                              void* d_out, int out_size)
{
    const float* x    = (const float*)d_in[0];
    const float* Wqkv = (const float*)d_in[1];
    const float* Wout = (const float*)d_in[2];
    float* out = (float*)d_out;

    static int attr_done = 0;
    if (!attr_done) {
        cudaFuncSetAttribute(gemm_mma_kernel<0>,
                             cudaFuncAttributeMaxDynamicSharedMemorySize, GEMM_SMEM);
        cudaFuncSetAttribute(gemm_mma_kernel<1>,
                             cudaFuncAttributeMaxDynamicSharedMemorySize, GEMM_SMEM);
        cudaFuncSetAttribute(flash_mma_kernel,
                             cudaFuncAttributeMaxDynamicSharedMemorySize, FLASH_SMEM);
        attr_done = 1;
    }

    // 0) fused pre-pass (round x + both weight transposes)
    prep_kernel<<<NXB + NQB + NOB, 256>>>(x, Wqkv, Wout);
    // 1) QKV projection -> g_Q/g_K/g_V (tf32-rounded)
    {
        dim3 grid(N_QKV / 128, NTOK / 128);   // 48 x 64
        gemm_mma_kernel<0><<<grid, 256, GEMM_SMEM>>>(nullptr, N_QKV);
    }
    // 2) flash attention (rope fused, Q in regs, pre-rounded K/V) -> g_Y
    {
        dim3 grid(T_SEQ / 64, BH);            // 8 x 256
        flash_mma_kernel<<<grid, 128, FLASH_SMEM>>>();
    }
    // 3) output projection
    {
        dim3 grid(DIMC / 128, NTOK / 128);    // 16 x 64
        gemm_mma_kernel<1><<<grid, 256, GEMM_SMEM>>>(out, DIMC);
    }
}